// round 3
// baseline (speedup 1.0000x reference)
#include <cuda_runtime.h>
#include <math.h>

#define TT   1024
#define DD   2048
#define DFF  1024
#define EE   16
#define KSLOT 6
#define TK   (TT*KSLOT)

// ---------------- scratch (device globals; no allocations allowed) ----------
__device__ int   g_count[EE];
__device__ int   g_cursor[EE];
__device__ int   g_off[EE + 1];
__device__ int   g_tok[TK];
__device__ float g_wt[TK];
// padded by one M-tile (128 rows) so pass-2 A-tile loads never go OOB
__device__ __align__(16) float g_H[(size_t)(TK + 128) * DFF];

// ---------------- pass 0: bucket (token,slot) pairs by expert ---------------
__global__ void k_zero() {
    int i = threadIdx.x;
    if (i < EE) { g_count[i] = 0; g_cursor[i] = 0; }
}

// NOTE: selected_experts is int32 on the wire (JAX x64 disabled downcasts
// jnp.int64 -> int32). Reading as int64 was the R1 illegal-access bug.
__global__ void k_count(const int* __restrict__ se) {
    int i = blockIdx.x * blockDim.x + threadIdx.x;
    if (i < TK) {
        int e = se[i] & (EE - 1);
        atomicAdd(&g_count[e], 1);
    }
}

__global__ void k_scan() {
    int s = 0;
    g_off[0] = 0;
    for (int e = 0; e < EE; e++) { s += g_count[e]; g_off[e + 1] = s; }
}

__global__ void k_scatter(const int* __restrict__ se,
                          const float* __restrict__ rw) {
    int i = blockIdx.x * blockDim.x + threadIdx.x;
    if (i < TK) {
        int e = se[i] & (EE - 1);
        int p = g_off[e] + atomicAdd(&g_cursor[e], 1);
        g_tok[p] = i / KSLOT;
        g_wt[p]  = rw[i];
    }
}

// ---------------- pass 1: H = silu(x@w0^T * s0) * (x@w1^T * s1) -------------
// NT GEMM, per expert. Block tile: 128 (M=pairs) x 64 (N=dff), K-tile 16.
// Computes gate AND up in the same block (shared A tile), fused SwiGLU.
#define TM1 128
#define TN1 64
#define TK1 16

__global__ __launch_bounds__(256, 2)
void k_gateup(const float* __restrict__ x,
              const float* __restrict__ w0,
              const float* __restrict__ w1,
              const float* __restrict__ s0,
              const float* __restrict__ s1) {
    int e   = blockIdx.z;
    int off = g_off[e], end = g_off[e + 1];
    int m0  = off + blockIdx.x * TM1;
    if (m0 >= end) return;
    int n0  = blockIdx.y * TN1;

    __shared__ __align__(16) float As[TK1][TM1];
    __shared__ __align__(16) float Bg[TK1][TN1];
    __shared__ __align__(16) float Bu[TK1][TN1];
    __shared__ int toks[TM1];

    int tid = threadIdx.x;
    if (tid < TM1) {
        int m = m0 + tid;
        toks[tid] = (m < end) ? g_tok[m] : -1;
    }
    __syncthreads();

    int tx = tid & 15;   // 16 threads over N, 4 cols each
    int ty = tid >> 4;   // 16 threads over M, 8 rows each

    float accg[8][4], accu[8][4];
#pragma unroll
    for (int i = 0; i < 8; i++)
#pragma unroll
        for (int j = 0; j < 4; j++) { accg[i][j] = 0.f; accu[i][j] = 0.f; }

    const float* w0e = w0 + (size_t)e * DFF * DD;
    const float* w1e = w1 + (size_t)e * DFF * DD;

    for (int k0 = 0; k0 < DD; k0 += TK1) {
        // A tile: 128x16 = 512 float4, 2 per thread
#pragma unroll
        for (int it = 0; it < 2; it++) {
            int lin = tid + it * 256;
            int m   = lin >> 2;
            int k4  = (lin & 3) * 4;
            int t   = toks[m];
            float4 v = make_float4(0.f, 0.f, 0.f, 0.f);
            if (t >= 0)
                v = *reinterpret_cast<const float4*>(x + (size_t)t * DD + k0 + k4);
            As[k4 + 0][m] = v.x; As[k4 + 1][m] = v.y;
            As[k4 + 2][m] = v.z; As[k4 + 3][m] = v.w;
        }
        // B tiles: 64x16 = 256 float4 each, 1 per thread
        {
            int n  = tid >> 2;
            int k4 = (tid & 3) * 4;
            size_t boff = (size_t)(n0 + n) * DD + k0 + k4;
            float4 v = *reinterpret_cast<const float4*>(w0e + boff);
            Bg[k4 + 0][n] = v.x; Bg[k4 + 1][n] = v.y;
            Bg[k4 + 2][n] = v.z; Bg[k4 + 3][n] = v.w;
            float4 u = *reinterpret_cast<const float4*>(w1e + boff);
            Bu[k4 + 0][n] = u.x; Bu[k4 + 1][n] = u.y;
            Bu[k4 + 2][n] = u.z; Bu[k4 + 3][n] = u.w;
        }
        __syncthreads();

#pragma unroll
        for (int k = 0; k < TK1; k++) {
            float4 a0 = *reinterpret_cast<const float4*>(&As[k][ty * 8]);
            float4 a1 = *reinterpret_cast<const float4*>(&As[k][ty * 8 + 4]);
            float4 bg = *reinterpret_cast<const float4*>(&Bg[k][tx * 4]);
            float4 bu = *reinterpret_cast<const float4*>(&Bu[k][tx * 4]);
            float a[8] = {a0.x, a0.y, a0.z, a0.w, a1.x, a1.y, a1.z, a1.w};
            float bgv[4] = {bg.x, bg.y, bg.z, bg.w};
            float buv[4] = {bu.x, bu.y, bu.z, bu.w};
#pragma unroll
            for (int i = 0; i < 8; i++)
#pragma unroll
                for (int j = 0; j < 4; j++) {
                    accg[i][j] += a[i] * bgv[j];
                    accu[i][j] += a[i] * buv[j];
                }
        }
        __syncthreads();
    }

    float sc0 = s0[e], sc1 = s1[e];
#pragma unroll
    for (int i = 0; i < 8; i++) {
        int m = m0 + ty * 8 + i;
        if (m >= end) continue;
        float h[4];
#pragma unroll
        for (int j = 0; j < 4; j++) {
            float g = accg[i][j] * sc0;
            float u = accu[i][j] * sc1;
            h[j] = (g / (1.f + expf(-g))) * u;   // silu(g) * u
        }
        float4* dst = reinterpret_cast<float4*>(g_H + (size_t)m * DFF + n0 + tx * 4);
        *dst = make_float4(h[0], h[1], h[2], h[3]);
    }
}

// ---------------- pass 2: out[tok] += wt*s2 * (H @ w2^T) --------------------
// NT GEMM, per expert. Block tile: 128 x 128, K-tile 16 over DFF.
#define TM2 128
#define TN2 128
#define TK2 16

__global__ __launch_bounds__(256, 1)
void k_down(const float* __restrict__ w2,
            const float* __restrict__ s2,
            float* __restrict__ out) {
    int e   = blockIdx.z;
    int off = g_off[e], end = g_off[e + 1];
    int m0  = off + blockIdx.x * TM2;
    if (m0 >= end) return;
    int n0  = blockIdx.y * TN2;

    __shared__ __align__(16) float As[TK2][TM2];
    __shared__ __align__(16) float Bs[TK2][TN2];

    int tid = threadIdx.x;
    int tx = tid & 15;   // N: 8 cols each
    int ty = tid >> 4;   // M: 8 rows each

    float acc[8][8];
#pragma unroll
    for (int i = 0; i < 8; i++)
#pragma unroll
        for (int j = 0; j < 8; j++) acc[i][j] = 0.f;

    const float* w2e = w2 + (size_t)e * DD * DFF;

    for (int k0 = 0; k0 < DFF; k0 += TK2) {
        // A tile: 128x16 (g_H is padded, unguarded loads safe)
#pragma unroll
        for (int it = 0; it < 2; it++) {
            int lin = tid + it * 256;
            int m   = lin >> 2;
            int k4  = (lin & 3) * 4;
            float4 v = *reinterpret_cast<const float4*>(
                g_H + (size_t)(m0 + m) * DFF + k0 + k4);
            As[k4 + 0][m] = v.x; As[k4 + 1][m] = v.y;
            As[k4 + 2][m] = v.z; As[k4 + 3][m] = v.w;
        }
        // B tile: 128x16
#pragma unroll
        for (int it = 0; it < 2; it++) {
            int lin = tid + it * 256;
            int n   = lin >> 2;
            int k4  = (lin & 3) * 4;
            float4 v = *reinterpret_cast<const float4*>(
                w2e + (size_t)(n0 + n) * DFF + k0 + k4);
            Bs[k4 + 0][n] = v.x; Bs[k4 + 1][n] = v.y;
            Bs[k4 + 2][n] = v.z; Bs[k4 + 3][n] = v.w;
        }
        __syncthreads();

#pragma unroll
        for (int k = 0; k < TK2; k++) {
            float4 a0 = *reinterpret_cast<const float4*>(&As[k][ty * 8]);
            float4 a1 = *reinterpret_cast<const float4*>(&As[k][ty * 8 + 4]);
            float4 b0 = *reinterpret_cast<const float4*>(&Bs[k][tx * 8]);
            float4 b1 = *reinterpret_cast<const float4*>(&Bs[k][tx * 8 + 4]);
            float a[8] = {a0.x, a0.y, a0.z, a0.w, a1.x, a1.y, a1.z, a1.w};
            float b[8] = {b0.x, b0.y, b0.z, b0.w, b1.x, b1.y, b1.z, b1.w};
#pragma unroll
            for (int i = 0; i < 8; i++)
#pragma unroll
                for (int j = 0; j < 8; j++)
                    acc[i][j] += a[i] * b[j];
        }
        __syncthreads();
    }

    float ws = s2[e];
#pragma unroll
    for (int i = 0; i < 8; i++) {
        int m = m0 + ty * 8 + i;
        if (m >= end) continue;
        int   t = g_tok[m];
        float w = g_wt[m] * ws;
        float* op = out + (size_t)t * DD + n0 + tx * 8;
#pragma unroll
        for (int j = 0; j < 8; j++)
            atomicAdd(op + j, w * acc[i][j]);
    }
}

// ---------------- launch ----------------------------------------------------
extern "C" void kernel_launch(void* const* d_in, const int* in_sizes, int n_in,
                              void* d_out, int out_size) {
    const float* x  = (const float*)d_in[0];
    const float* w0 = (const float*)d_in[1];
    const float* w1 = (const float*)d_in[2];
    const float* w2 = (const float*)d_in[3];
    const float* s0 = (const float*)d_in[4];
    const float* s1 = (const float*)d_in[5];
    const float* s2 = (const float*)d_in[6];
    const int*   se = (const int*)d_in[7];      // int32 (JAX x64 disabled)
    const float* rw = (const float*)d_in[8];
    float* out = (float*)d_out;

    cudaMemsetAsync(out, 0, (size_t)TT * DD * sizeof(float));

    k_zero<<<1, 32>>>();
    k_count<<<(TK + 255) / 256, 256>>>(se);
    k_scan<<<1, 1>>>();
    k_scatter<<<(TK + 255) / 256, 256>>>(se, rw);

    // Pass 1: grid covers worst-case M-tiles per expert (all pairs on one expert)
    dim3 g1((TK + TM1 - 1) / TM1, DFF / TN1, EE);
    k_gateup<<<g1, 256>>>(x, w0, w1, s0, s1);

    dim3 g2((TK + TM2 - 1) / TM2, DD / TN2, EE);
    k_down<<<g2, 256>>>(w2, s2, out);
}

// round 4
// speedup vs baseline: 2.7023x; 2.7023x over previous
#include <cuda_runtime.h>
#include <math.h>

#define TT    1024
#define DD    2048
#define DFF   1024
#define EE    16
#define KSLOT 6
#define TK    (TT*KSLOT)
#define MAXTILES 64

// ---------------- scratch (device globals; no allocations allowed) ----------
__device__ int   g_count[EE];
__device__ int   g_cursor[EE];
__device__ int   g_off[EE + 1];
__device__ int   g_tok[TK];      // pair p -> token
__device__ int   g_slot[TK];     // pair p -> original t*KSLOT+k index
__device__ float g_wt[TK];       // pair p -> routing weight
__device__ int   g_tile_e[MAXTILES];
__device__ int   g_tile_m0[MAXTILES];
__device__ int   g_ntiles;
// padded by one M-tile so pass-2 A-tile loads never go OOB
__device__ __align__(16) float g_H[(size_t)(TK + 128) * DFF];
// per-slot weighted down-proj results, reduced per-token at the end
__device__ __align__(16) float g_Y[(size_t)TK * DD];

// ---------------- helpers ----------------------------------------------------
__device__ __forceinline__ unsigned f2tf(float f) {
    unsigned u;
    asm("cvt.rna.tf32.f32 %0, %1;" : "=r"(u) : "f"(f));
    return u;
}

__device__ __forceinline__ void mma_tf32(float& d0, float& d1, float& d2, float& d3,
                                         unsigned a0, unsigned a1, unsigned a2, unsigned a3,
                                         unsigned b0, unsigned b1) {
    asm volatile(
        "mma.sync.aligned.m16n8k8.row.col.f32.tf32.tf32.f32 "
        "{%0,%1,%2,%3},{%4,%5,%6,%7},{%8,%9},{%0,%1,%2,%3};"
        : "+f"(d0), "+f"(d1), "+f"(d2), "+f"(d3)
        : "r"(a0), "r"(a1), "r"(a2), "r"(a3), "r"(b0), "r"(b1));
}

// ---------------- pass 0: bucket (token,slot) pairs by expert ---------------
__global__ void k_zero() {
    int i = threadIdx.x;
    if (i < EE) { g_count[i] = 0; g_cursor[i] = 0; }
}

// selected_experts arrives as int32 on the wire (JAX x64 disabled).
__global__ void k_count(const int* __restrict__ se) {
    int i = blockIdx.x * blockDim.x + threadIdx.x;
    if (i < TK) atomicAdd(&g_count[se[i] & (EE - 1)], 1);
}

__global__ void k_scan() {
    int s = 0, nt = 0;
    g_off[0] = 0;
    for (int e = 0; e < EE; e++) {
        int off = s;
        s += g_count[e];
        g_off[e + 1] = s;
        for (int m0 = off; m0 < s; m0 += 128) {
            g_tile_e[nt]  = e;
            g_tile_m0[nt] = m0;
            nt++;
        }
    }
    g_ntiles = nt;
}

__global__ void k_scatter(const int* __restrict__ se,
                          const float* __restrict__ rw) {
    int i = blockIdx.x * blockDim.x + threadIdx.x;
    if (i < TK) {
        int e = se[i] & (EE - 1);
        int p = g_off[e] + atomicAdd(&g_cursor[e], 1);
        g_tok[p]  = i / KSLOT;
        g_slot[p] = i;
        g_wt[p]   = rw[i];
    }
}

// ---------------- pass 1: H = silu(x@w0^T * s0) * (x@w1^T * s1) -------------
// tf32 mma.sync. Block tile 128(M pairs) x 64(N dff), both gate & up.
// 8 warps = 4(M) x 2(N); warp tile 32x32 per output.
#define KT 32
#define LDSW 36   // smem row stride (words): 36 ≡ 4 (mod 32) -> conflict-free frags

__global__ __launch_bounds__(256, 2)
void k_gateup(const float* __restrict__ x,
              const float* __restrict__ w0,
              const float* __restrict__ w1,
              const float* __restrict__ s0,
              const float* __restrict__ s1) {
    int tile = blockIdx.x;
    if (tile >= g_ntiles) return;
    int e   = g_tile_e[tile];
    int m0  = g_tile_m0[tile];
    int end = g_off[e + 1];
    int n0  = blockIdx.y * 64;

    __shared__ __align__(16) unsigned As[128][LDSW];
    __shared__ __align__(16) unsigned Bg[64][LDSW];
    __shared__ __align__(16) unsigned Bu[64][LDSW];
    __shared__ int toks[128];

    int tid = threadIdx.x;
    if (tid < 128) {
        int m = m0 + tid;
        toks[tid] = (m < end) ? g_tok[m] : -1;
    }
    __syncthreads();

    int w  = tid >> 5, L = tid & 31;
    int wm = w & 3, wn = w >> 2;
    int rm = wm * 32;         // warp row base
    int cn = wn * 32;         // warp col base

    float accg[2][4][4], accu[2][4][4];
#pragma unroll
    for (int i = 0; i < 2; i++)
#pragma unroll
        for (int j = 0; j < 4; j++)
#pragma unroll
            for (int q = 0; q < 4; q++) { accg[i][j][q] = 0.f; accu[i][j][q] = 0.f; }

    const float* w0e = w0 + (size_t)e * DFF * DD;
    const float* w1e = w1 + (size_t)e * DFF * DD;

    for (int k0 = 0; k0 < DD; k0 += KT) {
        // A: 128x32 -> 1024 float4, 4 per thread (token-gathered)
#pragma unroll
        for (int it = 0; it < 4; it++) {
            int lin = tid + it * 256;
            int m   = lin >> 3;
            int c4  = (lin & 7) * 4;
            int t   = toks[m];
            float4 v = make_float4(0.f, 0.f, 0.f, 0.f);
            if (t >= 0)
                v = *reinterpret_cast<const float4*>(x + (size_t)t * DD + k0 + c4);
            uint4 u = make_uint4(f2tf(v.x), f2tf(v.y), f2tf(v.z), f2tf(v.w));
            *reinterpret_cast<uint4*>(&As[m][c4]) = u;
        }
        // Bg/Bu: 64x32 -> 512 float4 each, 2 per thread each
#pragma unroll
        for (int it = 0; it < 2; it++) {
            int lin = tid + it * 256;
            int n   = lin >> 3;
            int c4  = (lin & 7) * 4;
            size_t boff = (size_t)(n0 + n) * DD + k0 + c4;
            float4 v = *reinterpret_cast<const float4*>(w0e + boff);
            *reinterpret_cast<uint4*>(&Bg[n][c4]) =
                make_uint4(f2tf(v.x), f2tf(v.y), f2tf(v.z), f2tf(v.w));
            float4 q = *reinterpret_cast<const float4*>(w1e + boff);
            *reinterpret_cast<uint4*>(&Bu[n][c4]) =
                make_uint4(f2tf(q.x), f2tf(q.y), f2tf(q.z), f2tf(q.w));
        }
        __syncthreads();

#pragma unroll
        for (int kk = 0; kk < KT; kk += 8) {
            unsigned a[2][4];
#pragma unroll
            for (int mt = 0; mt < 2; mt++) {
                int r = rm + mt * 16 + (L >> 2);
                int c = kk + (L & 3);
                a[mt][0] = As[r][c];
                a[mt][1] = As[r + 8][c];
                a[mt][2] = As[r][c + 4];
                a[mt][3] = As[r + 8][c + 4];
            }
#pragma unroll
            for (int nt = 0; nt < 4; nt++) {
                int col = cn + nt * 8 + (L >> 2);
                int c   = kk + (L & 3);
                unsigned bg0 = Bg[col][c], bg1 = Bg[col][c + 4];
                unsigned bu0 = Bu[col][c], bu1 = Bu[col][c + 4];
#pragma unroll
                for (int mt = 0; mt < 2; mt++) {
                    mma_tf32(accg[mt][nt][0], accg[mt][nt][1], accg[mt][nt][2], accg[mt][nt][3],
                             a[mt][0], a[mt][1], a[mt][2], a[mt][3], bg0, bg1);
                    mma_tf32(accu[mt][nt][0], accu[mt][nt][1], accu[mt][nt][2], accu[mt][nt][3],
                             a[mt][0], a[mt][1], a[mt][2], a[mt][3], bu0, bu1);
                }
            }
        }
        __syncthreads();
    }

    float sc0 = s0[e], sc1 = s1[e];
#pragma unroll
    for (int mt = 0; mt < 2; mt++) {
#pragma unroll
        for (int half = 0; half < 2; half++) {
            int row = rm + mt * 16 + (L >> 2) + half * 8;
            int m   = m0 + row;
            if (m >= end) continue;
#pragma unroll
            for (int nt = 0; nt < 4; nt++) {
                int col = cn + nt * 8 + (L & 3) * 2;
                float gv0 = accg[mt][nt][half * 2 + 0] * sc0;
                float gv1 = accg[mt][nt][half * 2 + 1] * sc0;
                float uv0 = accu[mt][nt][half * 2 + 0] * sc1;
                float uv1 = accu[mt][nt][half * 2 + 1] * sc1;
                float h0 = (gv0 / (1.f + expf(-gv0))) * uv0;
                float h1 = (gv1 / (1.f + expf(-gv1))) * uv1;
                *reinterpret_cast<float2*>(g_H + (size_t)m * DFF + n0 + col) =
                    make_float2(h0, h1);
            }
        }
    }
}

// ---------------- pass 2: Y[slot] = wt*s2 * (H @ w2^T) ----------------------
// tf32 mma.sync. Block tile 128 x 128. 8 warps = 4(M) x 2(N); warp 32x64.
__global__ __launch_bounds__(256, 2)
void k_down(const float* __restrict__ w2,
            const float* __restrict__ s2) {
    int tile = blockIdx.x;
    if (tile >= g_ntiles) return;
    int e   = g_tile_e[tile];
    int m0  = g_tile_m0[tile];
    int end = g_off[e + 1];
    int n0  = blockIdx.y * 128;

    __shared__ __align__(16) unsigned As[128][LDSW];
    __shared__ __align__(16) unsigned Bs[128][LDSW];

    int tid = threadIdx.x;
    int w  = tid >> 5, L = tid & 31;
    int wm = w & 3, wn = w >> 2;
    int rm = wm * 32;
    int cn = wn * 64;

    float acc[2][8][4];
#pragma unroll
    for (int i = 0; i < 2; i++)
#pragma unroll
        for (int j = 0; j < 8; j++)
#pragma unroll
            for (int q = 0; q < 4; q++) acc[i][j][q] = 0.f;

    const float* w2e = w2 + (size_t)e * DD * DFF;

    for (int k0 = 0; k0 < DFF; k0 += KT) {
        // A: 128x32 from g_H (padded -> unguarded)
#pragma unroll
        for (int it = 0; it < 4; it++) {
            int lin = tid + it * 256;
            int m   = lin >> 3;
            int c4  = (lin & 7) * 4;
            float4 v = *reinterpret_cast<const float4*>(
                g_H + (size_t)(m0 + m) * DFF + k0 + c4);
            *reinterpret_cast<uint4*>(&As[m][c4]) =
                make_uint4(f2tf(v.x), f2tf(v.y), f2tf(v.z), f2tf(v.w));
        }
        // B: 128x32
#pragma unroll
        for (int it = 0; it < 4; it++) {
            int lin = tid + it * 256;
            int n   = lin >> 3;
            int c4  = (lin & 7) * 4;
            float4 v = *reinterpret_cast<const float4*>(
                w2e + (size_t)(n0 + n) * DFF + k0 + c4);
            *reinterpret_cast<uint4*>(&Bs[n][c4]) =
                make_uint4(f2tf(v.x), f2tf(v.y), f2tf(v.z), f2tf(v.w));
        }
        __syncthreads();

#pragma unroll
        for (int kk = 0; kk < KT; kk += 8) {
            unsigned a[2][4];
#pragma unroll
            for (int mt = 0; mt < 2; mt++) {
                int r = rm + mt * 16 + (L >> 2);
                int c = kk + (L & 3);
                a[mt][0] = As[r][c];
                a[mt][1] = As[r + 8][c];
                a[mt][2] = As[r][c + 4];
                a[mt][3] = As[r + 8][c + 4];
            }
#pragma unroll
            for (int nt = 0; nt < 8; nt++) {
                int col = cn + nt * 8 + (L >> 2);
                int c   = kk + (L & 3);
                unsigned b0 = Bs[col][c], b1 = Bs[col][c + 4];
#pragma unroll
                for (int mt = 0; mt < 2; mt++)
                    mma_tf32(acc[mt][nt][0], acc[mt][nt][1], acc[mt][nt][2], acc[mt][nt][3],
                             a[mt][0], a[mt][1], a[mt][2], a[mt][3], b0, b1);
            }
        }
        __syncthreads();
    }

    float sce = s2[e];
#pragma unroll
    for (int mt = 0; mt < 2; mt++) {
#pragma unroll
        for (int half = 0; half < 2; half++) {
            int row = rm + mt * 16 + (L >> 2) + half * 8;
            int m   = m0 + row;
            if (m >= end) continue;
            int   slot = g_slot[m];
            float wv   = g_wt[m] * sce;
            float* yp  = g_Y + (size_t)slot * DD + n0;
#pragma unroll
            for (int nt = 0; nt < 8; nt++) {
                int col = cn + nt * 8 + (L & 3) * 2;
                *reinterpret_cast<float2*>(yp + col) =
                    make_float2(wv * acc[mt][nt][half * 2 + 0],
                                wv * acc[mt][nt][half * 2 + 1]);
            }
        }
    }
}

// ---------------- pass 3: out[t] = sum_k Y[t*6+k] ---------------------------
__global__ void k_reduce(float* __restrict__ out) {
    int i = blockIdx.x * blockDim.x + threadIdx.x;   // float4 index
    int t  = i / (DD / 4);
    int d4 = (i % (DD / 4)) * 4;
    const float* base = g_Y + (size_t)t * KSLOT * DD + d4;
    float4 acc = make_float4(0.f, 0.f, 0.f, 0.f);
#pragma unroll
    for (int k = 0; k < KSLOT; k++) {
        float4 v = *reinterpret_cast<const float4*>(base + (size_t)k * DD);
        acc.x += v.x; acc.y += v.y; acc.z += v.z; acc.w += v.w;
    }
    *reinterpret_cast<float4*>(out + (size_t)t * DD + d4) = acc;
}

// ---------------- launch ----------------------------------------------------
extern "C" void kernel_launch(void* const* d_in, const int* in_sizes, int n_in,
                              void* d_out, int out_size) {
    const float* x  = (const float*)d_in[0];
    const float* w0 = (const float*)d_in[1];
    const float* w1 = (const float*)d_in[2];
    const float* w2 = (const float*)d_in[3];
    const float* s0 = (const float*)d_in[4];
    const float* s1 = (const float*)d_in[5];
    const float* s2 = (const float*)d_in[6];
    const int*   se = (const int*)d_in[7];
    const float* rw = (const float*)d_in[8];
    float* out = (float*)d_out;

    k_zero<<<1, 32>>>();
    k_count<<<(TK + 255) / 256, 256>>>(se);
    k_scan<<<1, 1>>>();
    k_scatter<<<(TK + 255) / 256, 256>>>(se, rw);

    dim3 g1(MAXTILES, DFF / 64);
    k_gateup<<<g1, 256>>>(x, w0, w1, s0, s1);

    dim3 g2(MAXTILES, DD / 128);
    k_down<<<g2, 256>>>(w2, s2);

    k_reduce<<<(TT * DD / 4) / 256, 256>>>(out);
}

// round 5
// speedup vs baseline: 3.2301x; 1.1954x over previous
#include <cuda_runtime.h>
#include <math.h>

#define TT    1024
#define DD    2048
#define DFF   1024
#define EE    16
#define KSLOT 6
#define TK    (TT*KSLOT)
#define MAXTILES 64
#define KT    32
#define LDSW  36   // smem row stride (words); 36 % 32 = 4 -> conflict-free frags

// ---------------- scratch (device globals; no allocations allowed) ----------
__device__ int   g_count[EE];
__device__ int   g_cursor[EE];
__device__ int   g_off[EE + 1];
__device__ int   g_tok[TK];
__device__ int   g_slot[TK];
__device__ float g_wt[TK];
__device__ int   g_tile_e[MAXTILES];
__device__ int   g_tile_m0[MAXTILES];
__device__ int   g_ntiles;
__device__ __align__(16) float g_H[(size_t)(TK + 128) * DFF];
__device__ __align__(16) float g_Y[(size_t)TK * DD];

// ---------------- helpers ----------------------------------------------------
__device__ __forceinline__ unsigned f2tf(float f) {
    unsigned u;
    asm("cvt.rna.tf32.f32 %0, %1;" : "=r"(u) : "f"(f));
    return u;
}

__device__ __forceinline__ void mma_tf32(float& d0, float& d1, float& d2, float& d3,
                                         unsigned a0, unsigned a1, unsigned a2, unsigned a3,
                                         unsigned b0, unsigned b1) {
    asm volatile(
        "mma.sync.aligned.m16n8k8.row.col.f32.tf32.tf32.f32 "
        "{%0,%1,%2,%3},{%4,%5,%6,%7},{%8,%9},{%0,%1,%2,%3};"
        : "+f"(d0), "+f"(d1), "+f"(d2), "+f"(d3)
        : "r"(a0), "r"(a1), "r"(a2), "r"(a3), "r"(b0), "r"(b1));
}

__device__ __forceinline__ void cp16(const void* smem_dst, const void* gmem_src) {
    unsigned d = (unsigned)__cvta_generic_to_shared(smem_dst);
    asm volatile("cp.async.cg.shared.global [%0], [%1], 16;" :: "r"(d), "l"(gmem_src));
}
#define CP_COMMIT() asm volatile("cp.async.commit_group;")
#define CP_WAIT1()  asm volatile("cp.async.wait_group 1;")

// ---------------- pass 0: bucket (token,slot) pairs by expert ---------------
__global__ void k_zero() {
    int i = threadIdx.x;
    if (i < EE) { g_count[i] = 0; g_cursor[i] = 0; }
}

// selected_experts is int32 on the wire (JAX x64 disabled).
__global__ void k_count(const int* __restrict__ se) {
    int i = blockIdx.x * blockDim.x + threadIdx.x;
    if (i < TK) atomicAdd(&g_count[se[i] & (EE - 1)], 1);
}

__global__ void k_scan() {
    int s = 0, nt = 0;
    g_off[0] = 0;
    for (int e = 0; e < EE; e++) {
        int off = s;
        s += g_count[e];
        g_off[e + 1] = s;
        for (int m0 = off; m0 < s; m0 += 128) {
            g_tile_e[nt]  = e;
            g_tile_m0[nt] = m0;
            nt++;
        }
    }
    g_ntiles = nt;
}

__global__ void k_scatter(const int* __restrict__ se,
                          const float* __restrict__ rw) {
    int i = blockIdx.x * blockDim.x + threadIdx.x;
    if (i < TK) {
        int e = se[i] & (EE - 1);
        int p = g_off[e] + atomicAdd(&g_cursor[e], 1);
        g_tok[p]  = i / KSLOT;
        g_slot[p] = i;
        g_wt[p]   = rw[i];
    }
}

// ---------------- pass 1: H = silu(x@w0^T * s0) * (x@w1^T * s1) -------------
// 128(M) x 64(N) block tile, gate+up together; 8 warps = 4(M) x 2(N),
// warp tile 32x32 per output matrix. 2-stage cp.async pipeline, fp32 in smem.
#define P1_WORDS (2*128*LDSW + 4*64*LDSW)
#define P1_SMEM  (P1_WORDS*4 + 128*4)

__global__ __launch_bounds__(256, 2)
void k_gateup(const float* __restrict__ x,
              const float* __restrict__ w0,
              const float* __restrict__ w1,
              const float* __restrict__ s0,
              const float* __restrict__ s1) {
    int tile = blockIdx.x;
    if (tile >= g_ntiles) return;
    int e   = g_tile_e[tile];
    int m0  = g_tile_m0[tile];
    int end = g_off[e + 1];
    int n0  = blockIdx.y * 64;

    extern __shared__ float sm[];
    float (*As)[128][LDSW] = (float(*)[128][LDSW])sm;
    float (*Bg)[64][LDSW]  = (float(*)[64][LDSW])(sm + 2*128*LDSW);
    float (*Bu)[64][LDSW]  = (float(*)[64][LDSW])(sm + 2*128*LDSW + 2*64*LDSW);
    int*   toks            = (int*)(sm + P1_WORDS);

    int tid = threadIdx.x;
    if (tid < 128) {
        int m = m0 + tid;
        toks[tid] = (m < end) ? g_tok[m] : 0;  // clamp; garbage rows discarded later
    }
    __syncthreads();

    const float* w0e = w0 + (size_t)e * DFF * DD;
    const float* w1e = w1 + (size_t)e * DFF * DD;

    auto prefetch = [&](int s, int k0) {
#pragma unroll
        for (int it = 0; it < 4; it++) {
            int lin = tid + it * 256;
            int m   = lin >> 3;
            int c4  = (lin & 7) * 4;
            cp16(&As[s][m][c4], x + (size_t)toks[m] * DD + k0 + c4);
        }
#pragma unroll
        for (int it = 0; it < 2; it++) {
            int lin = tid + it * 256;
            int n   = lin >> 3;
            int c4  = (lin & 7) * 4;
            size_t boff = (size_t)(n0 + n) * DD + k0 + c4;
            cp16(&Bg[s][n][c4], w0e + boff);
            cp16(&Bu[s][n][c4], w1e + boff);
        }
    };

    int w  = tid >> 5, L = tid & 31;
    int wm = w & 3, wn = w >> 2;
    int rm = wm * 32, cn = wn * 32;

    float accg[2][4][4], accu[2][4][4];
#pragma unroll
    for (int i = 0; i < 2; i++)
#pragma unroll
        for (int j = 0; j < 4; j++)
#pragma unroll
            for (int q = 0; q < 4; q++) { accg[i][j][q] = 0.f; accu[i][j][q] = 0.f; }

    const int NT = DD / KT;   // 64
    prefetch(0, 0);
    CP_COMMIT();

    for (int it = 0; it < NT; it++) {
        if (it + 1 < NT) prefetch((it + 1) & 1, (it + 1) * KT);
        CP_COMMIT();
        CP_WAIT1();
        __syncthreads();
        int s = it & 1;

#pragma unroll
        for (int kk = 0; kk < KT; kk += 8) {
            unsigned a[2][4];
#pragma unroll
            for (int mt = 0; mt < 2; mt++) {
                int r = rm + mt * 16 + (L >> 2);
                int c = kk + (L & 3);
                a[mt][0] = f2tf(As[s][r][c]);
                a[mt][1] = f2tf(As[s][r + 8][c]);
                a[mt][2] = f2tf(As[s][r][c + 4]);
                a[mt][3] = f2tf(As[s][r + 8][c + 4]);
            }
#pragma unroll
            for (int nt = 0; nt < 4; nt++) {
                int col = cn + nt * 8 + (L >> 2);
                int c   = kk + (L & 3);
                unsigned bg0 = f2tf(Bg[s][col][c]), bg1 = f2tf(Bg[s][col][c + 4]);
                unsigned bu0 = f2tf(Bu[s][col][c]), bu1 = f2tf(Bu[s][col][c + 4]);
#pragma unroll
                for (int mt = 0; mt < 2; mt++) {
                    mma_tf32(accg[mt][nt][0], accg[mt][nt][1], accg[mt][nt][2], accg[mt][nt][3],
                             a[mt][0], a[mt][1], a[mt][2], a[mt][3], bg0, bg1);
                    mma_tf32(accu[mt][nt][0], accu[mt][nt][1], accu[mt][nt][2], accu[mt][nt][3],
                             a[mt][0], a[mt][1], a[mt][2], a[mt][3], bu0, bu1);
                }
            }
        }
        __syncthreads();
    }

    float sc0 = s0[e], sc1 = s1[e];
#pragma unroll
    for (int mt = 0; mt < 2; mt++) {
#pragma unroll
        for (int half = 0; half < 2; half++) {
            int row = rm + mt * 16 + (L >> 2) + half * 8;
            int m   = m0 + row;
            if (m >= end) continue;
#pragma unroll
            for (int nt = 0; nt < 4; nt++) {
                int col = cn + nt * 8 + (L & 3) * 2;
                float gv0 = accg[mt][nt][half * 2 + 0] * sc0;
                float gv1 = accg[mt][nt][half * 2 + 1] * sc0;
                float uv0 = accu[mt][nt][half * 2 + 0] * sc1;
                float uv1 = accu[mt][nt][half * 2 + 1] * sc1;
                float h0 = (gv0 / (1.f + expf(-gv0))) * uv0;
                float h1 = (gv1 / (1.f + expf(-gv1))) * uv1;
                *reinterpret_cast<float2*>(g_H + (size_t)m * DFF + n0 + col) =
                    make_float2(h0, h1);
            }
        }
    }
}

// ---------------- pass 2: Y[slot] = wt*s2 * (H @ w2^T) ----------------------
// 128x128 block tile; 8 warps = 4(M) x 2(N), warp 32x64. 2-stage cp.async.
#define P2_WORDS (4*128*LDSW)
#define P2_SMEM  (P2_WORDS*4)

__global__ __launch_bounds__(256, 2)
void k_down(const float* __restrict__ w2,
            const float* __restrict__ s2) {
    int tile = blockIdx.x;
    if (tile >= g_ntiles) return;
    int e   = g_tile_e[tile];
    int m0  = g_tile_m0[tile];
    int end = g_off[e + 1];
    int n0  = blockIdx.y * 128;

    extern __shared__ float sm[];
    float (*As)[128][LDSW] = (float(*)[128][LDSW])sm;
    float (*Bs)[128][LDSW] = (float(*)[128][LDSW])(sm + 2*128*LDSW);

    int tid = threadIdx.x;
    const float* w2e = w2 + (size_t)e * DD * DFF;

    auto prefetch = [&](int s, int k0) {
#pragma unroll
        for (int it = 0; it < 4; it++) {
            int lin = tid + it * 256;
            int m   = lin >> 3;
            int c4  = (lin & 7) * 4;
            cp16(&As[s][m][c4], g_H + (size_t)(m0 + m) * DFF + k0 + c4);
            cp16(&Bs[s][m][c4], w2e + (size_t)(n0 + m) * DFF + k0 + c4);
        }
    };

    int w  = tid >> 5, L = tid & 31;
    int wm = w & 3, wn = w >> 2;
    int rm = wm * 32, cn = wn * 64;

    float acc[2][8][4];
#pragma unroll
    for (int i = 0; i < 2; i++)
#pragma unroll
        for (int j = 0; j < 8; j++)
#pragma unroll
            for (int q = 0; q < 4; q++) acc[i][j][q] = 0.f;

    const int NT = DFF / KT;   // 32
    prefetch(0, 0);
    CP_COMMIT();

    for (int it = 0; it < NT; it++) {
        if (it + 1 < NT) prefetch((it + 1) & 1, (it + 1) * KT);
        CP_COMMIT();
        CP_WAIT1();
        __syncthreads();
        int s = it & 1;

#pragma unroll
        for (int kk = 0; kk < KT; kk += 8) {
            unsigned a[2][4];
#pragma unroll
            for (int mt = 0; mt < 2; mt++) {
                int r = rm + mt * 16 + (L >> 2);
                int c = kk + (L & 3);
                a[mt][0] = f2tf(As[s][r][c]);
                a[mt][1] = f2tf(As[s][r + 8][c]);
                a[mt][2] = f2tf(As[s][r][c + 4]);
                a[mt][3] = f2tf(As[s][r + 8][c + 4]);
            }
#pragma unroll
            for (int nt = 0; nt < 8; nt++) {
                int col = cn + nt * 8 + (L >> 2);
                int c   = kk + (L & 3);
                unsigned b0 = f2tf(Bs[s][col][c]), b1 = f2tf(Bs[s][col][c + 4]);
#pragma unroll
                for (int mt = 0; mt < 2; mt++)
                    mma_tf32(acc[mt][nt][0], acc[mt][nt][1], acc[mt][nt][2], acc[mt][nt][3],
                             a[mt][0], a[mt][1], a[mt][2], a[mt][3], b0, b1);
            }
        }
        __syncthreads();
    }

    float sce = s2[e];
#pragma unroll
    for (int mt = 0; mt < 2; mt++) {
#pragma unroll
        for (int half = 0; half < 2; half++) {
            int row = rm + mt * 16 + (L >> 2) + half * 8;
            int m   = m0 + row;
            if (m >= end) continue;
            int   slot = g_slot[m];
            float wv   = g_wt[m] * sce;
            float* yp  = g_Y + (size_t)slot * DD + n0;
#pragma unroll
            for (int nt = 0; nt < 8; nt++) {
                int col = cn + nt * 8 + (L & 3) * 2;
                *reinterpret_cast<float2*>(yp + col) =
                    make_float2(wv * acc[mt][nt][half * 2 + 0],
                                wv * acc[mt][nt][half * 2 + 1]);
            }
        }
    }
}

// ---------------- pass 3: out[t] = sum_k Y[t*6+k] ---------------------------
__global__ void k_reduce(float* __restrict__ out) {
    int i = blockIdx.x * blockDim.x + threadIdx.x;
    int t  = i / (DD / 4);
    int d4 = (i % (DD / 4)) * 4;
    const float* base = g_Y + (size_t)t * KSLOT * DD + d4;
    float4 acc = make_float4(0.f, 0.f, 0.f, 0.f);
#pragma unroll
    for (int k = 0; k < KSLOT; k++) {
        float4 v = *reinterpret_cast<const float4*>(base + (size_t)k * DD);
        acc.x += v.x; acc.y += v.y; acc.z += v.z; acc.w += v.w;
    }
    *reinterpret_cast<float4*>(out + (size_t)t * DD + d4) = acc;
}

// ---------------- launch ----------------------------------------------------
extern "C" void kernel_launch(void* const* d_in, const int* in_sizes, int n_in,
                              void* d_out, int out_size) {
    const float* x  = (const float*)d_in[0];
    const float* w0 = (const float*)d_in[1];
    const float* w1 = (const float*)d_in[2];
    const float* w2 = (const float*)d_in[3];
    const float* s0 = (const float*)d_in[4];
    const float* s1 = (const float*)d_in[5];
    const float* s2 = (const float*)d_in[6];
    const int*   se = (const int*)d_in[7];
    const float* rw = (const float*)d_in[8];
    float* out = (float*)d_out;

    static bool attr_set = false;
    if (!attr_set) {
        cudaFuncSetAttribute(k_gateup, cudaFuncAttributeMaxDynamicSharedMemorySize, P1_SMEM);
        cudaFuncSetAttribute(k_down,   cudaFuncAttributeMaxDynamicSharedMemorySize, P2_SMEM);
        attr_set = true;
    }

    k_zero<<<1, 32>>>();
    k_count<<<(TK + 255) / 256, 256>>>(se);
    k_scan<<<1, 1>>>();
    k_scatter<<<(TK + 255) / 256, 256>>>(se, rw);

    dim3 g1(MAXTILES, DFF / 64);
    k_gateup<<<g1, 256, P1_SMEM>>>(x, w0, w1, s0, s1);

    dim3 g2(MAXTILES, DD / 128);
    k_down<<<g2, 256, P2_SMEM>>>(w2, s2);

    k_reduce<<<(TT * DD / 4) / 256, 256>>>(out);
}